// round 14
// baseline (speedup 1.0000x reference)
#include <cuda_runtime.h>

// Reverse cummax along axis 1 of [B=16, H=128, W=128, C=256] fp32.
// out[b,h,w,c] = max_{h'>=h} in[b,h',w,c]
//
// FINAL — converged, 5x replicated on identical source:
//   kernel 80.4/79.5/82.7/80.3/79.1us, DRAM 76.5/77.7/74.6/76.7/77.8%
//   (rounds R1/R10/R11/R12/R13). +/-2% run variance brackets every
//   variant difference observed across the session.
//
// Configuration: one thread per (b, w, c4) float4 column, register running
// max, h=127..0, interleaved load/max/store, unroll 4, block 256 /
// grid 512, no cache hints, regs=28.
//
// Plateau evidence: MLP 1..8 (explicit pipeline: neutral), 4KB phase-
// batched R/W bursts (neutral), .STREAM hints (-3..-16%), block 128
// (regression). 512MB of DRAM traffic is the provable minimum for this
// op; issue=5% rules out any SM-side limit; 6.0-6.2 TB/s is this part's
// mixed read/write memory-controller ceiling. Kernel is at its roofline.

static constexpr int B = 16;
static constexpr int H = 128;
static constexpr int W = 128;
static constexpr int C = 256;
static constexpr int C4 = C / 4;                 // 64 float4 per (w) row
static constexpr int PLANE4 = W * C4;            // 8192 float4 per (b,h) slice
static constexpr int HSTRIDE4 = PLANE4;
static constexpr int NCOL = B * W * C4;          // 131072 columns

__global__ __launch_bounds__(256) void suffix_cummax_kernel(
    const float4* __restrict__ in, float4* __restrict__ out)
{
    int col = blockIdx.x * blockDim.x + threadIdx.x;  // grid covers exactly NCOL

    // col -> (b, w, c4): c4 fastest
    int c4 = col & (C4 - 1);
    int w  = (col >> 6) & (W - 1);       // C4 = 2^6
    int b  = col >> 13;                  // W*C4 = 2^13

    // whole tensor is 16M float4 -> int indexing is safe
    int base = b * (H * PLANE4) + w * C4 + c4;

    const float4* ip = in  + base + (H - 1) * HSTRIDE4;
    float4*       op = out + base + (H - 1) * HSTRIDE4;

    float4 run;
    run.x = -__int_as_float(0x7f800000);  // -inf
    run.y = run.x; run.z = run.x; run.w = run.x;

    #pragma unroll 4
    for (int h = H - 1; h >= 0; --h) {
        float4 v = *ip;
        run.x = fmaxf(run.x, v.x);
        run.y = fmaxf(run.y, v.y);
        run.z = fmaxf(run.z, v.z);
        run.w = fmaxf(run.w, v.w);
        *op = run;
        ip -= HSTRIDE4;
        op -= HSTRIDE4;
    }
}

extern "C" void kernel_launch(void* const* d_in, const int* in_sizes, int n_in,
                              void* d_out, int out_size)
{
    const float4* in  = (const float4*)d_in[0];
    float4*       out = (float4*)d_out;

    int threads = 256;
    int blocks  = NCOL / threads;  // 512, exact
    suffix_cummax_kernel<<<blocks, threads>>>(in, out);
}

// round 15
// speedup vs baseline: 1.0117x; 1.0117x over previous
#include <cuda_runtime.h>

// Reverse cummax along axis 1 of [B=16, H=128, W=128, C=256] fp32.
// out[b,h,w,c] = max_{h'>=h} in[b,h',w,c]
//
// FINAL — converged, 6x replicated on identical source:
//   kernel 80.4/79.5/82.7/80.3/79.1/81.2us
//   DRAM   76.5/77.7/74.6/76.7/77.8/75.8%
//   (rounds R1/R10/R11/R12/R13/R14). +/-2% run variance brackets every
//   variant difference observed across the session.
//
// Configuration: one thread per (b, w, c4) float4 column, register running
// max, h=127..0, interleaved load/max/store, unroll 4, block 256 /
// grid 512, no cache hints, regs=28.
//
// Plateau evidence: MLP 1..8 (explicit pipeline: neutral), 4KB phase-
// batched R/W bursts (neutral), .STREAM hints (-3..-16%), block 128
// (regression). 512MB of DRAM traffic is the provable minimum for this
// op; issue=5% rules out any SM-side limit; 6.0-6.2 TB/s is this part's
// mixed read/write memory-controller ceiling. Kernel is at its roofline.

static constexpr int B = 16;
static constexpr int H = 128;
static constexpr int W = 128;
static constexpr int C = 256;
static constexpr int C4 = C / 4;                 // 64 float4 per (w) row
static constexpr int PLANE4 = W * C4;            // 8192 float4 per (b,h) slice
static constexpr int HSTRIDE4 = PLANE4;
static constexpr int NCOL = B * W * C4;          // 131072 columns

__global__ __launch_bounds__(256) void suffix_cummax_kernel(
    const float4* __restrict__ in, float4* __restrict__ out)
{
    int col = blockIdx.x * blockDim.x + threadIdx.x;  // grid covers exactly NCOL

    // col -> (b, w, c4): c4 fastest
    int c4 = col & (C4 - 1);
    int w  = (col >> 6) & (W - 1);       // C4 = 2^6
    int b  = col >> 13;                  // W*C4 = 2^13

    // whole tensor is 16M float4 -> int indexing is safe
    int base = b * (H * PLANE4) + w * C4 + c4;

    const float4* ip = in  + base + (H - 1) * HSTRIDE4;
    float4*       op = out + base + (H - 1) * HSTRIDE4;

    float4 run;
    run.x = -__int_as_float(0x7f800000);  // -inf
    run.y = run.x; run.z = run.x; run.w = run.x;

    #pragma unroll 4
    for (int h = H - 1; h >= 0; --h) {
        float4 v = *ip;
        run.x = fmaxf(run.x, v.x);
        run.y = fmaxf(run.y, v.y);
        run.z = fmaxf(run.z, v.z);
        run.w = fmaxf(run.w, v.w);
        *op = run;
        ip -= HSTRIDE4;
        op -= HSTRIDE4;
    }
}

extern "C" void kernel_launch(void* const* d_in, const int* in_sizes, int n_in,
                              void* d_out, int out_size)
{
    const float4* in  = (const float4*)d_in[0];
    float4*       out = (float4*)d_out;

    int threads = 256;
    int blocks  = NCOL / threads;  // 512, exact
    suffix_cummax_kernel<<<blocks, threads>>>(in, out);
}